// round 12
// baseline (speedup 1.0000x reference)
#include <cuda_runtime.h>
#include <cuda_fp16.h>
#include <mma.h>
#include <math.h>
#include <stdint.h>

using namespace nvcuda;

// Problem constants: N=100000, F=256, UNITS=256, DIM=128
#define F_DIM   256
#define UNITS   256
#define DIM     128
#define N_MAX   100000
#define M_TILE  64
#define THREADS 256
#define LDA     264          // A smem leading dim (halfs), 528B stride
#define LDB     72           // B smem leading dim (halfs), 144B stride
#define LDC     260          // C smem leading dim (floats), 1040B stride
#define KC      64           // K chunk per pipeline stage
#define NCHUNK  (F_DIM / KC) // 4
#define NBUF    2            // pipeline depth

// Scratch
__device__ __half g_xh[(size_t)N_MAX * UNITS];   // packed [mean|var] fp16, ~51 MB
__device__ int    g_rowptr[N_MAX + 1];
__device__ float  g_kl;
__device__ __half g_Wh[UNITS * F_DIM];           // W^T fp16, [n][k]

__device__ __forceinline__ uint32_t smem_u32(const void* p) {
    uint32_t a;
    asm("{ .reg .u64 t; cvta.to.shared.u64 t, %1; cvt.u32.u64 %0, t; }"
        : "=r"(a) : "l"(p));
    return a;
}
__device__ __forceinline__ void cp_async16(uint32_t dst, const void* src) {
    asm volatile("cp.async.cg.shared.global [%0], [%1], 16;"
                 :: "r"(dst), "l"(src) : "memory");
}
#define CP_COMMIT()  asm volatile("cp.async.commit_group;" ::: "memory")
#define CP_WAIT(n)   asm volatile("cp.async.wait_group %0;" :: "n"(n) : "memory")

// ---------------------------------------------------------------------------
// Kernel 1: W fp16 transpose only (+ kl zero). Tiny: 65536 elements.
// ---------------------------------------------------------------------------
__global__ void prep_kernel(const float* __restrict__ W) {
    const int i = blockIdx.x * blockDim.x + threadIdx.x;
    if (i == 0) g_kl = 0.0f;
    if (i < UNITS * F_DIM) {
        const int nn = i / F_DIM, kk = i % F_DIM;
        g_Wh[i] = __float2half(W[kk * UNITS + nn]);
    }
}

// ---------------------------------------------------------------------------
// Kernel 2: single-pass fp16 WMMA GEMM + fused rowptr scatter.
// The CSR scatter (independent of GEMM data) runs between the chunk-0
// cp.async issue and A staging, hidden under the async-load latency.
// 256 thr (8 warps), M_TILE=64, 2 CTAs/SM. Warp owns 32 rows x 64 cols.
// ---------------------------------------------------------------------------
__global__ __launch_bounds__(THREADS, 2) void gemm_wmma_kernel(
    const float* __restrict__ feat, const int* __restrict__ row,
    int n, int e)
{
    extern __shared__ char smem[];
    __half* Ah = reinterpret_cast<__half*>(smem);        // 64*264*2 = 33792 B
    __half* Bbase = Ah + M_TILE * LDA;                   // 2 bufs x 18432 halfs
    float* C = reinterpret_cast<float*>(smem);           // epilogue reuse

    const int tid = threadIdx.x;
    const int wid = tid >> 5, lane = tid & 31;
    const int row0 = blockIdx.x * M_TILE;
    const int nrows = min(M_TILE, n - row0);

    const int BUF_ELEMS = 256 * LDB;

    // prefetch B chunk 0 (256 n-rows x 64 k)
    {
        __half* Bh = Bbase;
#pragma unroll
        for (int it = 0; it < 8; it++) {
            const int g = it * THREADS + tid;            // 0..2047
            const int nn = g >> 3;                       // 0..255
            const int k8 = (g & 7) << 3;                 // 0..56
            cp_async16(smem_u32(Bh + nn * LDB + k8), g_Wh + (size_t)nn * F_DIM + k8);
        }
        CP_COMMIT();
    }

    // --- fused CSR rowptr scatter (grid-stride over edge boundaries) ---
    {
        const int stride = gridDim.x * THREADS;
        for (int i = blockIdx.x * THREADS + tid; i <= e; i += stride) {
            const int prev = (i == 0) ? -1 : __ldg(&row[i - 1]);
            const int cur  = (i == e) ? n  : __ldg(&row[i]);
            for (int j = prev + 1; j <= cur; j++) g_rowptr[j] = i;
        }
    }

    // --- stage A: fp32 -> fp16 ---
#pragma unroll
    for (int it = 0; it < 16; it++) {
        const int j = it * THREADS + tid;                // float4 id, 0..4095
        const int r = j >> 6;                            // row 0..63
        const int c4 = (j & 63) << 2;
        float4 v = make_float4(0.f, 0.f, 0.f, 0.f);
        if (r < nrows)
            v = reinterpret_cast<const float4*>(feat + (size_t)(row0 + r) * F_DIM)[j & 63];
        __half2 p0; p0.x = __float2half(v.x); p0.y = __float2half(v.y);
        __half2 p1; p1.x = __float2half(v.z); p1.y = __float2half(v.w);
        reinterpret_cast<__half2*>(Ah + r * LDA + c4)[0] = p0;
        reinterpret_cast<__half2*>(Ah + r * LDA + c4)[1] = p1;
    }

    const int rg = wid >> 2;            // 0..1 (32-row group)
    const int cg = wid & 3;             // 0..3 (64-col group)

    wmma::fragment<wmma::accumulator, 16, 16, 16, float> acc[2][4];
#pragma unroll
    for (int i = 0; i < 2; i++)
#pragma unroll
        for (int j = 0; j < 4; j++) wmma::fill_fragment(acc[i][j], 0.0f);

    CP_WAIT(0);
    __syncthreads();

    // --- double-buffered mainloop over 4 K-chunks of 64 ---
    for (int c = 0; c < NCHUNK; c++) {
        const int kc = c * KC;
        if (c < NCHUNK - 1) {            // prefetch chunk c+1
            __half* Bh = Bbase + ((c + 1) & 1) * BUF_ELEMS;
            const int kcn = kc + KC;
#pragma unroll
            for (int it = 0; it < 8; it++) {
                const int g = it * THREADS + tid;
                const int nn = g >> 3;
                const int k8 = (g & 7) << 3;
                cp_async16(smem_u32(Bh + nn * LDB + k8),
                           g_Wh + (size_t)nn * F_DIM + kcn + k8);
            }
            CP_COMMIT();
        }

        const __half* Bh = Bbase + (c & 1) * BUF_ELEMS;
#pragma unroll
        for (int ks = 0; ks < KC; ks += 16) {
            wmma::fragment<wmma::matrix_a, 16, 16, 16, __half, wmma::row_major> fah[2];
#pragma unroll
            for (int i = 0; i < 2; i++)
                wmma::load_matrix_sync(fah[i], Ah + (rg * 32 + i * 16) * LDA + kc + ks, LDA);
#pragma unroll
            for (int j = 0; j < 4; j++) {
                const int ncol = cg * 64 + j * 16;
                wmma::fragment<wmma::matrix_b, 16, 16, 16, __half, wmma::col_major> fbh;
                wmma::load_matrix_sync(fbh, Bh + ncol * LDB + ks, LDB);
                wmma::mma_sync(acc[0][j], fah[0], fbh, acc[0][j]);
                wmma::mma_sync(acc[1][j], fah[1], fbh, acc[1][j]);
            }
        }

        if (c < NCHUNK - 1) {
            CP_WAIT(0);
            __syncthreads();
        }
    }
    __syncthreads();   // smem no longer needed as A/B; reuse as C

#pragma unroll
    for (int i = 0; i < 2; i++)
#pragma unroll
        for (int j = 0; j < 4; j++)
            wmma::store_matrix_sync(C + (rg * 32 + i * 16) * LDC + cg * 64 + j * 16,
                                    acc[i][j], LDC, wmma::mem_row_major);
    __syncthreads();

    // --- epilogue: activations via MUFU, KL; g_x in fp16 ---
    float kl = 0.f;
#pragma unroll
    for (int it = 0; it < 16; it++) {
        const int idx = it * THREADS + tid;              // 0..4095
        const int r = idx >> 6;                          // 0..63
        const int d2 = (idx & 63) << 1;                  // even d, 0..126
        if (r < nrows) {
            float mo[2], vo[2];
#pragma unroll
            for (int q = 0; q < 2; q++) {
                const float hm = C[r * LDC + d2 + q];
                const float hv = C[r * LDC + DIM + d2 + q];
                const float m = hm > 0.f ? hm : (__expf(hm) - 1.0f);
                const float v = hv > 0.f ? hv : 0.f;
                const float att = __expf(-v);
                kl += m * m + v - __logf(1e-8f + v) - 1.f;
                mo[q] = m * att;
                vo[q] = v * att * att;
            }
            const size_t base = (size_t)(row0 + r) * UNITS;
            __half2 hm2; hm2.x = __float2half(mo[0]); hm2.y = __float2half(mo[1]);
            __half2 hv2; hv2.x = __float2half(vo[0]); hv2.y = __float2half(vo[1]);
            *reinterpret_cast<__half2*>(g_xh + base + d2)       = hm2;
            *reinterpret_cast<__half2*>(g_xh + base + DIM + d2) = hv2;
        }
    }
    kl *= 0.5f / (float)DIM;

    __shared__ float kl_red[8];
#pragma unroll
    for (int off = 16; off > 0; off >>= 1)
        kl += __shfl_down_sync(0xFFFFFFFFu, kl, off);
    if (lane == 0) kl_red[wid] = kl;
    __syncthreads();
    if (tid == 0) {
        float s = 0.f;
#pragma unroll
        for (int i = 0; i < 8; i++) s += kl_red[i];
        atomicAdd(&g_kl, s);
    }
}

// ---------------------------------------------------------------------------
// Kernel 3: fused dual SpMM on fp16 table, 8-way unrolled gathers for MLP.
// ONE warp per node: lanes 0-15 = mean half (adj1), lanes 16-31 = var (adj2).
// ---------------------------------------------------------------------------
__global__ void spmm_kernel(
    const int* __restrict__ col,
    const float* __restrict__ a1,
    const float* __restrict__ a2,
    float* __restrict__ out,
    int n, int write_kl)
{
    const int gtid = blockIdx.x * blockDim.x + threadIdx.x;
    if (gtid == 0 && write_kl) out[(size_t)n * UNITS] = g_kl;

    const int node = gtid >> 5;
    const int lane = threadIdx.x & 31;
    if (node >= n) return;

    const int s = g_rowptr[node];
    const int e = g_rowptr[node + 1];
    const float* __restrict__ wa = (lane < 16) ? a1 : a2;

    float acc[8];
#pragma unroll
    for (int q = 0; q < 8; q++) acc[q] = 0.f;

    int i = s;
    for (; i + 7 < e; i += 8) {
        int   c[8];
        float w[8];
        uint4 x[8];
#pragma unroll
        for (int u = 0; u < 8; u++) { c[u] = __ldg(&col[i + u]); w[u] = __ldg(&wa[i + u]); }
#pragma unroll
        for (int u = 0; u < 8; u++)
            x[u] = __ldg(reinterpret_cast<const uint4*>(g_xh + (size_t)c[u] * UNITS) + lane);
#pragma unroll
        for (int u = 0; u < 8; u++) {
            const __half2* hp = reinterpret_cast<const __half2*>(&x[u]);
#pragma unroll
            for (int q = 0; q < 4; q++) {
                const float2 f = __half22float2(hp[q]);
                acc[2 * q]     = fmaf(w[u], f.x, acc[2 * q]);
                acc[2 * q + 1] = fmaf(w[u], f.y, acc[2 * q + 1]);
            }
        }
    }
    for (; i < e; i++) {
        const int c0 = __ldg(&col[i]);
        const float w0 = __ldg(&wa[i]);
        const uint4 x0 = __ldg(reinterpret_cast<const uint4*>(g_xh + (size_t)c0 * UNITS) + lane);
        const __half2* hp = reinterpret_cast<const __half2*>(&x0);
#pragma unroll
        for (int q = 0; q < 4; q++) {
            const float2 f = __half22float2(hp[q]);
            acc[2 * q]     = fmaf(w0, f.x, acc[2 * q]);
            acc[2 * q + 1] = fmaf(w0, f.y, acc[2 * q + 1]);
        }
    }

    float* o = out + (size_t)node * UNITS + lane * 8;
    *reinterpret_cast<float4*>(o)     = make_float4(acc[0], acc[1], acc[2], acc[3]);
    *reinterpret_cast<float4*>(o + 4) = make_float4(acc[4], acc[5], acc[6], acc[7]);
}

// ---------------------------------------------------------------------------
extern "C" void kernel_launch(void* const* d_in, const int* in_sizes, int n_in,
                              void* d_out, int out_size) {
    const float* feat = (const float*)d_in[0];
    const float* W    = (const float*)d_in[1];
    const int*   row  = (const int*)d_in[2];
    const int*   col  = (const int*)d_in[3];
    const float* a1   = (const float*)d_in[4];
    const float* a2   = (const float*)d_in[5];
    float* out = (float*)d_out;

    const int n = in_sizes[0] / F_DIM;
    const int e = in_sizes[2];
    const int write_kl = (out_size > n * UNITS) ? 1 : 0;

    {   // W transpose/round (tiny)
        const int threads = 256;
        prep_kernel<<<(UNITS * F_DIM + threads - 1) / threads, threads>>>(W);
    }
    {   // fp16 WMMA GEMM + fused rowptr scatter + epilogue (2 CTAs/SM)
        const int smem_total = M_TILE * LDA * 2 + NBUF * (256 * LDB) * 2; // 107520
        cudaFuncSetAttribute(gemm_wmma_kernel,
                             cudaFuncAttributeMaxDynamicSharedMemorySize, smem_total);
        gemm_wmma_kernel<<<(n + M_TILE - 1) / M_TILE, THREADS, smem_total>>>(feat, row, n, e);
    }
    {   // dual SpMM, 1 warp per node
        const int threads = 256;
        spmm_kernel<<<(n * 32 + threads - 1) / threads, threads>>>(col, a1, a2, out, n, write_kl);
    }
}

// round 14
// speedup vs baseline: 1.0282x; 1.0282x over previous
#include <cuda_runtime.h>
#include <cuda_fp16.h>
#include <mma.h>
#include <math.h>
#include <stdint.h>

using namespace nvcuda;

// Problem constants: N=100000, F=256, UNITS=256, DIM=128
#define F_DIM   256
#define UNITS   256
#define DIM     128
#define N_MAX   100000
#define M_TILE  64
#define THREADS 256
#define LDA     264          // A smem leading dim (halfs), 528B stride
#define LDB     72           // B smem leading dim (halfs), 144B stride
#define LDC     260          // C smem leading dim (floats), 1040B stride
#define KC      64           // K chunk per pipeline stage
#define NCHUNK  (F_DIM / KC) // 4
#define NBUF    2            // pipeline depth
#define GRID_P  296          // persistent grid: 2 CTAs x 148 SMs

// Static chunk->buffer map. CRITICAL: chunk 0 -> buf 1, because the epilogue
// overlaps smem C [0, 66560) with A+buf0; the chunk-0 prefetch that flies
// during the epilogue must land in buf1 [70656, 107520), disjoint from C.
#define CHUNK_BUF(c) (((c) & 1) ^ 1)

// Scratch
__device__ __half g_xh[(size_t)N_MAX * UNITS];   // packed [mean|var] fp16, ~51 MB
__device__ int    g_rowptr[N_MAX + 1];
__device__ float  g_kl;
__device__ __half g_Wh[UNITS * F_DIM];           // W^T fp16, [n][k]

__device__ __forceinline__ uint32_t smem_u32(const void* p) {
    uint32_t a;
    asm("{ .reg .u64 t; cvta.to.shared.u64 t, %1; cvt.u32.u64 %0, t; }"
        : "=r"(a) : "l"(p));
    return a;
}
__device__ __forceinline__ void cp_async16(uint32_t dst, const void* src) {
    asm volatile("cp.async.cg.shared.global [%0], [%1], 16;"
                 :: "r"(dst), "l"(src) : "memory");
}
#define CP_COMMIT()  asm volatile("cp.async.commit_group;" ::: "memory")
#define CP_WAIT(n)   asm volatile("cp.async.wait_group %0;" :: "n"(n) : "memory")

// ---------------------------------------------------------------------------
// Kernel 1: CSR row_ptr scatter (+ kl zero) fused with W fp16 transpose
// ---------------------------------------------------------------------------
__global__ void prep_kernel(const int* __restrict__ row,
                            const float* __restrict__ W, int n, int e) {
    const int i = blockIdx.x * blockDim.x + threadIdx.x;
    if (i == 0) g_kl = 0.0f;
    if (i < UNITS * F_DIM) {      // W transpose + fp16 round
        const int nn = i / F_DIM, kk = i % F_DIM;
        g_Wh[i] = __float2half(W[kk * UNITS + nn]);
    }
    if (i > e) return;            // rowptr boundary scatter
    int prev = (i == 0) ? -1 : row[i - 1];
    int cur  = (i == e) ? n  : row[i];
    for (int j = prev + 1; j <= cur; j++) g_rowptr[j] = i;
}

// ---------------------------------------------------------------------------
// Kernel 2: persistent single-pass fp16 WMMA GEMM.
// Grid = 296 CTAs (2/SM); each grid-strides over M-tiles. B pipeline runs
// continuously across tiles (chunk sequence cycles 0,1,2,3,0,...): tile t+1's
// chunk-0 load overlaps tile t's epilogue + A staging. No wave tail.
// ---------------------------------------------------------------------------
__global__ __launch_bounds__(THREADS, 2) void gemm_wmma_kernel(
    const float* __restrict__ feat, int n, int ntiles)
{
    extern __shared__ char smem[];
    __half* Ah = reinterpret_cast<__half*>(smem);        // [0, 33792)
    __half* Bbase = Ah + M_TILE * LDA;                   // buf0 [33792,70656), buf1 [70656,107520)
    float* C = reinterpret_cast<float*>(smem);           // [0, 66560) = A + buf0 only

    const int tid = threadIdx.x;
    const int wid = tid >> 5, lane = tid & 31;
    const int rg = wid >> 2;            // 0..1 (32-row group)
    const int cg = wid & 3;             // 0..3 (64-col group)
    const int BUF_ELEMS = 256 * LDB;

    // initial prefetch: chunk 0 -> buf CHUNK_BUF(0) = buf1
    {
        __half* Bh = Bbase + CHUNK_BUF(0) * BUF_ELEMS;
#pragma unroll
        for (int it = 0; it < 8; it++) {
            const int g = it * THREADS + tid;
            const int nn = g >> 3;
            const int k8 = (g & 7) << 3;
            cp_async16(smem_u32(Bh + nn * LDB + k8), g_Wh + (size_t)nn * F_DIM + k8);
        }
        CP_COMMIT();
    }

    float kl = 0.f;             // accumulated across tiles

    for (int tile = blockIdx.x; tile < ntiles; tile += gridDim.x) {
        const int row0 = tile * M_TILE;
        const int nrows = min(M_TILE, n - row0);
        const bool tile_has_next = (tile + gridDim.x) < ntiles;

        // --- stage A: fp32 -> fp16 (chunk-0 cp.async flying underneath) ---
#pragma unroll
        for (int it = 0; it < 16; it++) {
            const int j = it * THREADS + tid;            // float4 id, 0..4095
            const int r = j >> 6;                        // row 0..63
            const int c4 = (j & 63) << 2;
            float4 v = make_float4(0.f, 0.f, 0.f, 0.f);
            if (r < nrows)
                v = reinterpret_cast<const float4*>(feat + (size_t)(row0 + r) * F_DIM)[j & 63];
            __half2 p0; p0.x = __float2half(v.x); p0.y = __float2half(v.y);
            __half2 p1; p1.x = __float2half(v.z); p1.y = __float2half(v.w);
            reinterpret_cast<__half2*>(Ah + r * LDA + c4)[0] = p0;
            reinterpret_cast<__half2*>(Ah + r * LDA + c4)[1] = p1;
        }

        wmma::fragment<wmma::accumulator, 16, 16, 16, float> acc[2][4];
#pragma unroll
        for (int i = 0; i < 2; i++)
#pragma unroll
            for (int j = 0; j < 4; j++) wmma::fill_fragment(acc[i][j], 0.0f);

        // --- chunk loop; invariant: chunk c in-flight/landed in buf CHUNK_BUF(c) ---
        for (int c = 0; c < NCHUNK; c++) {
            CP_WAIT(0);
            __syncthreads();   // chunk c landed; prior readers of target buf done

            const bool have_next = (c < NCHUNK - 1) || tile_has_next;
            if (have_next) {   // prefetch chunk (c+1)%4 into its static buffer
                const int cn = (c + 1) & (NCHUNK - 1);
                const int kcn = cn * KC;
                __half* Bh = Bbase + CHUNK_BUF(cn) * BUF_ELEMS;
#pragma unroll
                for (int it = 0; it < 8; it++) {
                    const int g = it * THREADS + tid;
                    const int nn = g >> 3;
                    const int k8 = (g & 7) << 3;
                    cp_async16(smem_u32(Bh + nn * LDB + k8),
                               g_Wh + (size_t)nn * F_DIM + kcn + k8);
                }
                CP_COMMIT();
            }

            const int kc = c * KC;
            const __half* Bh = Bbase + CHUNK_BUF(c) * BUF_ELEMS;
#pragma unroll
            for (int ks = 0; ks < KC; ks += 16) {
                wmma::fragment<wmma::matrix_a, 16, 16, 16, __half, wmma::row_major> fah[2];
#pragma unroll
                for (int i = 0; i < 2; i++)
                    wmma::load_matrix_sync(fah[i], Ah + (rg * 32 + i * 16) * LDA + kc + ks, LDA);
#pragma unroll
                for (int j = 0; j < 4; j++) {
                    const int ncol = cg * 64 + j * 16;
                    wmma::fragment<wmma::matrix_b, 16, 16, 16, __half, wmma::col_major> fbh;
                    wmma::load_matrix_sync(fbh, Bh + ncol * LDB + ks, LDB);
                    wmma::mma_sync(acc[0][j], fah[0], fbh, acc[0][j]);
                    wmma::mma_sync(acc[1][j], fah[1], fbh, acc[1][j]);
                }
            }
        }
        __syncthreads();   // all MMAs done; A+buf0 free -> use as C.
        // chunk-0 prefetch (if any) is in flight into buf1, disjoint from C.

#pragma unroll
        for (int i = 0; i < 2; i++)
#pragma unroll
            for (int j = 0; j < 4; j++)
                wmma::store_matrix_sync(C + (rg * 32 + i * 16) * LDC + cg * 64 + j * 16,
                                        acc[i][j], LDC, wmma::mem_row_major);
        __syncthreads();

        // --- epilogue: activations via MUFU, KL; g_x in fp16 ---
#pragma unroll
        for (int it = 0; it < 16; it++) {
            const int idx = it * THREADS + tid;          // 0..4095
            const int r = idx >> 6;                      // 0..63
            const int d2 = (idx & 63) << 1;              // even d, 0..126
            if (r < nrows) {
                float mo[2], vo[2];
#pragma unroll
                for (int q = 0; q < 2; q++) {
                    const float hm = C[r * LDC + d2 + q];
                    const float hv = C[r * LDC + DIM + d2 + q];
                    const float m = hm > 0.f ? hm : (__expf(hm) - 1.0f);
                    const float v = hv > 0.f ? hv : 0.f;
                    const float att = __expf(-v);
                    kl += m * m + v - __logf(1e-8f + v) - 1.f;
                    mo[q] = m * att;
                    vo[q] = v * att * att;
                }
                const size_t base = (size_t)(row0 + r) * UNITS;
                __half2 hm2; hm2.x = __float2half(mo[0]); hm2.y = __float2half(mo[1]);
                __half2 hv2; hv2.x = __float2half(vo[0]); hv2.y = __float2half(vo[1]);
                *reinterpret_cast<__half2*>(g_xh + base + d2)       = hm2;
                *reinterpret_cast<__half2*>(g_xh + base + DIM + d2) = hv2;
            }
        }
        __syncthreads();   // C reads done before next tile overwrites A region
    }

    // --- final KL reduction (once per CTA) ---
    kl *= 0.5f / (float)DIM;
    __shared__ float kl_red[8];
#pragma unroll
    for (int off = 16; off > 0; off >>= 1)
        kl += __shfl_down_sync(0xFFFFFFFFu, kl, off);
    if (lane == 0) kl_red[wid] = kl;
    __syncthreads();
    if (tid == 0) {
        float s = 0.f;
#pragma unroll
        for (int i = 0; i < 8; i++) s += kl_red[i];
        atomicAdd(&g_kl, s);
    }
}

// ---------------------------------------------------------------------------
// Kernel 3: fused dual SpMM on fp16 table (unroll-4).
// ONE warp per node: lanes 0-15 = mean half (adj1), lanes 16-31 = var (adj2).
// ---------------------------------------------------------------------------
__global__ void spmm_kernel(
    const int* __restrict__ col,
    const float* __restrict__ a1,
    const float* __restrict__ a2,
    float* __restrict__ out,
    int n, int write_kl)
{
    const int gtid = blockIdx.x * blockDim.x + threadIdx.x;
    if (gtid == 0 && write_kl) out[(size_t)n * UNITS] = g_kl;

    const int node = gtid >> 5;
    const int lane = threadIdx.x & 31;
    if (node >= n) return;

    const int s = g_rowptr[node];
    const int e = g_rowptr[node + 1];
    const float* __restrict__ wa = (lane < 16) ? a1 : a2;

    float acc[8];
#pragma unroll
    for (int q = 0; q < 8; q++) acc[q] = 0.f;

    int i = s;
    for (; i + 3 < e; i += 4) {
        int   c[4];
        float w[4];
        uint4 x[4];
#pragma unroll
        for (int u = 0; u < 4; u++) { c[u] = __ldg(&col[i + u]); w[u] = __ldg(&wa[i + u]); }
#pragma unroll
        for (int u = 0; u < 4; u++)
            x[u] = __ldg(reinterpret_cast<const uint4*>(g_xh + (size_t)c[u] * UNITS) + lane);
#pragma unroll
        for (int u = 0; u < 4; u++) {
            const __half2* hp = reinterpret_cast<const __half2*>(&x[u]);
#pragma unroll
            for (int q = 0; q < 4; q++) {
                const float2 f = __half22float2(hp[q]);
                acc[2 * q]     = fmaf(w[u], f.x, acc[2 * q]);
                acc[2 * q + 1] = fmaf(w[u], f.y, acc[2 * q + 1]);
            }
        }
    }
    for (; i < e; i++) {
        const int c0 = __ldg(&col[i]);
        const float w0 = __ldg(&wa[i]);
        const uint4 x0 = __ldg(reinterpret_cast<const uint4*>(g_xh + (size_t)c0 * UNITS) + lane);
        const __half2* hp = reinterpret_cast<const __half2*>(&x0);
#pragma unroll
        for (int q = 0; q < 4; q++) {
            const float2 f = __half22float2(hp[q]);
            acc[2 * q]     = fmaf(w0, f.x, acc[2 * q]);
            acc[2 * q + 1] = fmaf(w0, f.y, acc[2 * q + 1]);
        }
    }

    float* o = out + (size_t)node * UNITS + lane * 8;
    *reinterpret_cast<float4*>(o)     = make_float4(acc[0], acc[1], acc[2], acc[3]);
    *reinterpret_cast<float4*>(o + 4) = make_float4(acc[4], acc[5], acc[6], acc[7]);
}

// ---------------------------------------------------------------------------
extern "C" void kernel_launch(void* const* d_in, const int* in_sizes, int n_in,
                              void* d_out, int out_size) {
    const float* feat = (const float*)d_in[0];
    const float* W    = (const float*)d_in[1];
    const int*   row  = (const int*)d_in[2];
    const int*   col  = (const int*)d_in[3];
    const float* a1   = (const float*)d_in[4];
    const float* a2   = (const float*)d_in[5];
    float* out = (float*)d_out;

    const int n = in_sizes[0] / F_DIM;
    const int e = in_sizes[2];
    const int write_kl = (out_size > n * UNITS) ? 1 : 0;

    {   // fused prep: rowptr scatter + W transpose/round
        const int threads = 256;
        const int work = (e + 1 > UNITS * F_DIM) ? e + 1 : UNITS * F_DIM;
        prep_kernel<<<(work + threads - 1) / threads, threads>>>(row, W, n, e);
    }
    {   // persistent fp16 WMMA GEMM + epilogue (107.5KB smem, 2 CTAs/SM)
        const int ntiles = (n + M_TILE - 1) / M_TILE;
        const int grid = ntiles < GRID_P ? ntiles : GRID_P;
        const int smem_total = M_TILE * LDA * 2 + NBUF * (256 * LDB) * 2; // 107520
        cudaFuncSetAttribute(gemm_wmma_kernel,
                             cudaFuncAttributeMaxDynamicSharedMemorySize, smem_total);
        gemm_wmma_kernel<<<grid, THREADS, smem_total>>>(feat, n, ntiles);
    }
    {   // dual SpMM, 1 warp per node
        const int threads = 256;
        spmm_kernel<<<(n * 32 + threads - 1) / threads, threads>>>(col, a1, a2, out, n, write_kl);
    }
}

// round 15
// speedup vs baseline: 1.0531x; 1.0242x over previous
#include <cuda_runtime.h>
#include <cuda_fp16.h>
#include <mma.h>
#include <math.h>
#include <stdint.h>

using namespace nvcuda;

// Problem constants: N=100000, F=256, UNITS=256, DIM=128
#define F_DIM   256
#define UNITS   256
#define DIM     128
#define N_MAX   100000
#define M_TILE  64
#define THREADS 256
#define LDA     264          // A smem leading dim (halfs), 528B stride
#define LDB     72           // B smem leading dim (halfs), 144B stride
#define LDC     260          // C smem leading dim (floats), 1040B stride
#define KC      64           // K chunk per pipeline stage
#define NCHUNK  (F_DIM / KC) // 4
#define NBUF    2            // pipeline depth
#define GRID_P  296          // persistent grid: 2 CTAs x 148 SMs

// Static chunk->buffer map. CRITICAL: chunk 0 -> buf 1, because the epilogue
// overlaps smem C [0, 66560) with A+buf0; the chunk-0 prefetch that flies
// during the epilogue must land in buf1 [70656, 107520), disjoint from C.
#define CHUNK_BUF(c) (((c) & 1) ^ 1)

// Scratch
__device__ __half g_xh[(size_t)N_MAX * UNITS];   // packed [mean|var] fp16, ~51 MB
__device__ int    g_rowptr[N_MAX + 1];
__device__ float  g_kl;
__device__ __half g_Wh[UNITS * F_DIM];           // W^T fp16, [n][k]

__device__ __forceinline__ uint32_t smem_u32(const void* p) {
    uint32_t a;
    asm("{ .reg .u64 t; cvta.to.shared.u64 t, %1; cvt.u32.u64 %0, t; }"
        : "=r"(a) : "l"(p));
    return a;
}
__device__ __forceinline__ void cp_async16(uint32_t dst, const void* src) {
    asm volatile("cp.async.cg.shared.global [%0], [%1], 16;"
                 :: "r"(dst), "l"(src) : "memory");
}
#define CP_COMMIT()  asm volatile("cp.async.commit_group;" ::: "memory")
#define CP_WAIT(n)   asm volatile("cp.async.wait_group %0;" :: "n"(n) : "memory")

// ---------------------------------------------------------------------------
// Kernel 1: W fp16 transpose + kl zero + VECTORIZED CSR rowptr scatter.
// One thread handles 4 edge boundaries (int4 load); ~4x fewer instructions
// than the 1-boundary-per-thread version (which was issue-bound at 9.3us).
// ---------------------------------------------------------------------------
__global__ void prep_kernel(const int* __restrict__ row,
                            const float* __restrict__ W, int n, int e) {
    const int i = blockIdx.x * blockDim.x + threadIdx.x;
    if (i == 0) g_kl = 0.0f;
    if (i < UNITS * F_DIM) {      // W transpose + fp16 round
        const int nn = i / F_DIM, kk = i % F_DIM;
        g_Wh[i] = __float2half(W[kk * UNITS + nn]);
    }
    // rowptr scatter: thread i covers boundaries j in [4i, 4i+4) ∩ [0, e]
    const int j0 = i * 4;
    if (j0 > e) return;
    // values row[j0-1 .. j0+3]; row[-1] := -1 sentinel, row[e] := n
    int r[5];
    r[0] = (j0 == 0) ? -1 : __ldg(&row[j0 - 1]);
    if (j0 + 3 < e) {
        const int4 v = *reinterpret_cast<const int4*>(row + j0);  // 16B aligned
        r[1] = v.x; r[2] = v.y; r[3] = v.z; r[4] = v.w;
    } else {
#pragma unroll
        for (int u = 0; u < 4; u++)
            r[1 + u] = (j0 + u < e) ? __ldg(&row[j0 + u]) : n;
    }
#pragma unroll
    for (int u = 0; u < 4; u++) {
        const int j = j0 + u;
        if (j > e) break;
        const int prev = r[u];
        const int cur  = (j == e) ? n : r[u + 1];
        for (int k = prev + 1; k <= cur; k++) g_rowptr[k] = j;
    }
}

// ---------------------------------------------------------------------------
// Kernel 2: persistent single-pass fp16 WMMA GEMM (unchanged from R14).
// Grid = 296 CTAs (2/SM); B pipeline runs continuously across tiles.
// ---------------------------------------------------------------------------
__global__ __launch_bounds__(THREADS, 2) void gemm_wmma_kernel(
    const float* __restrict__ feat, int n, int ntiles)
{
    extern __shared__ char smem[];
    __half* Ah = reinterpret_cast<__half*>(smem);        // [0, 33792)
    __half* Bbase = Ah + M_TILE * LDA;                   // buf0 [33792,70656), buf1 [70656,107520)
    float* C = reinterpret_cast<float*>(smem);           // [0, 66560) = A + buf0 only

    const int tid = threadIdx.x;
    const int wid = tid >> 5, lane = tid & 31;
    const int rg = wid >> 2;            // 0..1 (32-row group)
    const int cg = wid & 3;             // 0..3 (64-col group)
    const int BUF_ELEMS = 256 * LDB;

    // initial prefetch: chunk 0 -> buf CHUNK_BUF(0) = buf1
    {
        __half* Bh = Bbase + CHUNK_BUF(0) * BUF_ELEMS;
#pragma unroll
        for (int it = 0; it < 8; it++) {
            const int g = it * THREADS + tid;
            const int nn = g >> 3;
            const int k8 = (g & 7) << 3;
            cp_async16(smem_u32(Bh + nn * LDB + k8), g_Wh + (size_t)nn * F_DIM + k8);
        }
        CP_COMMIT();
    }

    float kl = 0.f;             // accumulated across tiles

    for (int tile = blockIdx.x; tile < ntiles; tile += gridDim.x) {
        const int row0 = tile * M_TILE;
        const int nrows = min(M_TILE, n - row0);
        const bool tile_has_next = (tile + gridDim.x) < ntiles;

        // --- stage A: fp32 -> fp16 (chunk-0 cp.async flying underneath) ---
#pragma unroll
        for (int it = 0; it < 16; it++) {
            const int j = it * THREADS + tid;            // float4 id, 0..4095
            const int r = j >> 6;                        // row 0..63
            const int c4 = (j & 63) << 2;
            float4 v = make_float4(0.f, 0.f, 0.f, 0.f);
            if (r < nrows)
                v = reinterpret_cast<const float4*>(feat + (size_t)(row0 + r) * F_DIM)[j & 63];
            __half2 p0; p0.x = __float2half(v.x); p0.y = __float2half(v.y);
            __half2 p1; p1.x = __float2half(v.z); p1.y = __float2half(v.w);
            reinterpret_cast<__half2*>(Ah + r * LDA + c4)[0] = p0;
            reinterpret_cast<__half2*>(Ah + r * LDA + c4)[1] = p1;
        }

        wmma::fragment<wmma::accumulator, 16, 16, 16, float> acc[2][4];
#pragma unroll
        for (int i = 0; i < 2; i++)
#pragma unroll
            for (int j = 0; j < 4; j++) wmma::fill_fragment(acc[i][j], 0.0f);

        // --- chunk loop; invariant: chunk c in-flight/landed in buf CHUNK_BUF(c) ---
        for (int c = 0; c < NCHUNK; c++) {
            CP_WAIT(0);
            __syncthreads();   // chunk c landed; prior readers of target buf done

            const bool have_next = (c < NCHUNK - 1) || tile_has_next;
            if (have_next) {   // prefetch chunk (c+1)%4 into its static buffer
                const int cn = (c + 1) & (NCHUNK - 1);
                const int kcn = cn * KC;
                __half* Bh = Bbase + CHUNK_BUF(cn) * BUF_ELEMS;
#pragma unroll
                for (int it = 0; it < 8; it++) {
                    const int g = it * THREADS + tid;
                    const int nn = g >> 3;
                    const int k8 = (g & 7) << 3;
                    cp_async16(smem_u32(Bh + nn * LDB + k8),
                               g_Wh + (size_t)nn * F_DIM + kcn + k8);
                }
                CP_COMMIT();
            }

            const int kc = c * KC;
            const __half* Bh = Bbase + CHUNK_BUF(c) * BUF_ELEMS;
#pragma unroll
            for (int ks = 0; ks < KC; ks += 16) {
                wmma::fragment<wmma::matrix_a, 16, 16, 16, __half, wmma::row_major> fah[2];
#pragma unroll
                for (int i = 0; i < 2; i++)
                    wmma::load_matrix_sync(fah[i], Ah + (rg * 32 + i * 16) * LDA + kc + ks, LDA);
#pragma unroll
                for (int j = 0; j < 4; j++) {
                    const int ncol = cg * 64 + j * 16;
                    wmma::fragment<wmma::matrix_b, 16, 16, 16, __half, wmma::col_major> fbh;
                    wmma::load_matrix_sync(fbh, Bh + ncol * LDB + ks, LDB);
                    wmma::mma_sync(acc[0][j], fah[0], fbh, acc[0][j]);
                    wmma::mma_sync(acc[1][j], fah[1], fbh, acc[1][j]);
                }
            }
        }
        __syncthreads();   // all MMAs done; A+buf0 free -> use as C.
        // chunk-0 prefetch (if any) is in flight into buf1, disjoint from C.

#pragma unroll
        for (int i = 0; i < 2; i++)
#pragma unroll
            for (int j = 0; j < 4; j++)
                wmma::store_matrix_sync(C + (rg * 32 + i * 16) * LDC + cg * 64 + j * 16,
                                        acc[i][j], LDC, wmma::mem_row_major);
        __syncthreads();

        // --- epilogue: activations via MUFU, KL; g_x in fp16 ---
#pragma unroll
        for (int it = 0; it < 16; it++) {
            const int idx = it * THREADS + tid;          // 0..4095
            const int r = idx >> 6;                      // 0..63
            const int d2 = (idx & 63) << 1;              // even d, 0..126
            if (r < nrows) {
                float mo[2], vo[2];
#pragma unroll
                for (int q = 0; q < 2; q++) {
                    const float hm = C[r * LDC + d2 + q];
                    const float hv = C[r * LDC + DIM + d2 + q];
                    const float m = hm > 0.f ? hm : (__expf(hm) - 1.0f);
                    const float v = hv > 0.f ? hv : 0.f;
                    const float att = __expf(-v);
                    kl += m * m + v - __logf(1e-8f + v) - 1.f;
                    mo[q] = m * att;
                    vo[q] = v * att * att;
                }
                const size_t base = (size_t)(row0 + r) * UNITS;
                __half2 hm2; hm2.x = __float2half(mo[0]); hm2.y = __float2half(mo[1]);
                __half2 hv2; hv2.x = __float2half(vo[0]); hv2.y = __float2half(vo[1]);
                *reinterpret_cast<__half2*>(g_xh + base + d2)       = hm2;
                *reinterpret_cast<__half2*>(g_xh + base + DIM + d2) = hv2;
            }
        }
        __syncthreads();   // C reads done before next tile overwrites A region
    }

    // --- final KL reduction (once per CTA) ---
    kl *= 0.5f / (float)DIM;
    __shared__ float kl_red[8];
#pragma unroll
    for (int off = 16; off > 0; off >>= 1)
        kl += __shfl_down_sync(0xFFFFFFFFu, kl, off);
    if (lane == 0) kl_red[wid] = kl;
    __syncthreads();
    if (tid == 0) {
        float s = 0.f;
#pragma unroll
        for (int i = 0; i < 8; i++) s += kl_red[i];
        atomicAdd(&g_kl, s);
    }
}

// ---------------------------------------------------------------------------
// Kernel 3: fused dual SpMM on fp16 table (unroll-4).
// ONE warp per node: lanes 0-15 = mean half (adj1), lanes 16-31 = var (adj2).
// Output stored with __stcs (evict-first) so the streaming 102MB of writes
// doesn't evict the 51MB g_xh gather table from L2. Edge reads stay __ldg.
// ---------------------------------------------------------------------------
__global__ void spmm_kernel(
    const int* __restrict__ col,
    const float* __restrict__ a1,
    const float* __restrict__ a2,
    float* __restrict__ out,
    int n, int write_kl)
{
    const int gtid = blockIdx.x * blockDim.x + threadIdx.x;
    if (gtid == 0 && write_kl) out[(size_t)n * UNITS] = g_kl;

    const int node = gtid >> 5;
    const int lane = threadIdx.x & 31;
    if (node >= n) return;

    const int s = g_rowptr[node];
    const int e = g_rowptr[node + 1];
    const float* __restrict__ wa = (lane < 16) ? a1 : a2;

    float acc[8];
#pragma unroll
    for (int q = 0; q < 8; q++) acc[q] = 0.f;

    int i = s;
    for (; i + 3 < e; i += 4) {
        int   c[4];
        float w[4];
        uint4 x[4];
#pragma unroll
        for (int u = 0; u < 4; u++) { c[u] = __ldg(&col[i + u]); w[u] = __ldg(&wa[i + u]); }
#pragma unroll
        for (int u = 0; u < 4; u++)
            x[u] = __ldg(reinterpret_cast<const uint4*>(g_xh + (size_t)c[u] * UNITS) + lane);
#pragma unroll
        for (int u = 0; u < 4; u++) {
            const __half2* hp = reinterpret_cast<const __half2*>(&x[u]);
#pragma unroll
            for (int q = 0; q < 4; q++) {
                const float2 f = __half22float2(hp[q]);
                acc[2 * q]     = fmaf(w[u], f.x, acc[2 * q]);
                acc[2 * q + 1] = fmaf(w[u], f.y, acc[2 * q + 1]);
            }
        }
    }
    for (; i < e; i++) {
        const int c0 = __ldg(&col[i]);
        const float w0 = __ldg(&wa[i]);
        const uint4 x0 = __ldg(reinterpret_cast<const uint4*>(g_xh + (size_t)c0 * UNITS) + lane);
        const __half2* hp = reinterpret_cast<const __half2*>(&x0);
#pragma unroll
        for (int q = 0; q < 4; q++) {
            const float2 f = __half22float2(hp[q]);
            acc[2 * q]     = fmaf(w0, f.x, acc[2 * q]);
            acc[2 * q + 1] = fmaf(w0, f.y, acc[2 * q + 1]);
        }
    }

    float* o = out + (size_t)node * UNITS + lane * 8;
    __stcs(reinterpret_cast<float4*>(o),     make_float4(acc[0], acc[1], acc[2], acc[3]));
    __stcs(reinterpret_cast<float4*>(o + 4), make_float4(acc[4], acc[5], acc[6], acc[7]));
}

// ---------------------------------------------------------------------------
extern "C" void kernel_launch(void* const* d_in, const int* in_sizes, int n_in,
                              void* d_out, int out_size) {
    const float* feat = (const float*)d_in[0];
    const float* W    = (const float*)d_in[1];
    const int*   row  = (const int*)d_in[2];
    const int*   col  = (const int*)d_in[3];
    const float* a1   = (const float*)d_in[4];
    const float* a2   = (const float*)d_in[5];
    float* out = (float*)d_out;

    const int n = in_sizes[0] / F_DIM;
    const int e = in_sizes[2];
    const int write_kl = (out_size > n * UNITS) ? 1 : 0;

    {   // fused prep: vectorized rowptr scatter + W transpose/round
        const int threads = 256;
        const int scatter_threads = (e + 4) / 4 + 1;
        const int work = (scatter_threads > UNITS * F_DIM) ? scatter_threads : UNITS * F_DIM;
        prep_kernel<<<(work + threads - 1) / threads, threads>>>(row, W, n, e);
    }
    {   // persistent fp16 WMMA GEMM + epilogue (107.5KB smem, 2 CTAs/SM)
        const int ntiles = (n + M_TILE - 1) / M_TILE;
        const int grid = ntiles < GRID_P ? ntiles : GRID_P;
        const int smem_total = M_TILE * LDA * 2 + NBUF * (256 * LDB) * 2; // 107520
        cudaFuncSetAttribute(gemm_wmma_kernel,
                             cudaFuncAttributeMaxDynamicSharedMemorySize, smem_total);
        gemm_wmma_kernel<<<grid, THREADS, smem_total>>>(feat, n, ntiles);
    }
    {   // dual SpMM, 1 warp per node
        const int threads = 256;
        spmm_kernel<<<(n * 32 + threads - 1) / threads, threads>>>(col, a1, a2, out, n, write_kl);
    }
}